// round 5
// baseline (speedup 1.0000x reference)
#include <cuda_runtime.h>
#include <math.h>

// Problem constants (fixed by the dataset)
#define DIM     2048
#define SEQ     8192
#define NBLK    32                // blocks; each owns DIM/NBLK = 64 dims
#define TPB     256               // 16 token-groups x 16 dim-lanes
#define NLANE   16                // lanes per group; 16 * float4 = 64 dims
#define NGRP    16                // token groups per block
// Truncation: keep tokens with weight d^t > 2^-20 (~1e-6). Truncated tail
// contributes ~1e-6 of the state's magnitude — worst-case per-element
// relative error ~3e-6..1e-5, ~100-1000x under the 1e-3 tolerance.
#define TCUT    20.0f

__device__ __forceinline__ float sigmoidf_(float x) {
    return 1.0f / (1.0f + expf(-x));
}

// out[dim] = tanh( (1-d) * sum_{t=0..ntok-1} d^t * emb[idx[SEQ-1-t]][dim] )
__global__ void __launch_bounds__(TPB)
impulse_fused_kernel(const int* __restrict__ idx,
                     const float* __restrict__ emb,
                     const float* __restrict__ ssm_decay,
                     float* __restrict__ out)
{
    __shared__ float4 red[NGRP - 1][NLANE];

    const int lane = threadIdx.x & (NLANE - 1);   // dim lane within block
    const int tg   = threadIdx.x >> 4;            // token group 0..15

    const int dim = blockIdx.x * (NLANE * 4) + lane * 4;

    const float d   = sigmoidf_(ssm_decay[0]);
    const float l2d = log2f(d);                   // <= 0 since 0 < d <= 1

    // Number of newest tokens whose weight d^t stays above 2^-TCUT.
    // (If d == 1, l2d == 0 -> nt = inf -> ntok = SEQ; loop still correct,
    //  and (1-d) == 0 makes the output exactly tanh(0) = 0 like the ref.)
    const float nt = TCUT / (-l2d);
    int ntok = (nt >= (float)SEQ) ? SEQ : ((int)nt + 1);

    const float wstep = exp2f((float)NGRP * l2d); // d^16
    float w = exp2f((float)tg * l2d);             // d^tg

    float ax = 0.0f, ay = 0.0f, az = 0.0f, aw = 0.0f;

    // Typical case: ntok ~ 41 -> <= 3 iterations. All idx loads issue
    // independently (L1 broadcasts across the 16 lanes of a group), and
    // all emb loads depend only on their own idx -> two exposed latencies.
    #pragma unroll 4
    for (int t = tg; t < ntok; t += NGRP) {
        const long long row =
            (long long)__ldg(idx + (SEQ - 1 - t)) * (long long)DIM;
        const float4 x = *reinterpret_cast<const float4*>(emb + row + dim);
        ax = fmaf(w, x.x, ax);
        ay = fmaf(w, x.y, ay);
        az = fmaf(w, x.z, az);
        aw = fmaf(w, x.w, aw);
        w *= wstep;
    }

    // Cross-group reduction in shared memory (fixed order -> deterministic).
    if (tg > 0) {
        float4 v; v.x = ax; v.y = ay; v.z = az; v.w = aw;
        red[tg - 1][lane] = v;
    }
    __syncthreads();

    if (tg == 0) {
        #pragma unroll
        for (int g = 0; g < NGRP - 1; ++g) {
            const float4 v = red[g][lane];
            ax += v.x; ay += v.y; az += v.z; aw += v.w;
        }
        const float s = 1.0f - d;
        float4 o;
        o.x = tanhf(s * ax);
        o.y = tanhf(s * ay);
        o.z = tanhf(s * az);
        o.w = tanhf(s * aw);
        *reinterpret_cast<float4*>(out + dim) = o;
    }
}

extern "C" void kernel_launch(void* const* d_in, const int* in_sizes, int n_in,
                              void* d_out, int out_size)
{
    const int*   indices   = (const int*)d_in[0];
    const float* embedding = (const float*)d_in[1];
    const float* ssm_decay = (const float*)d_in[2];
    float*       out       = (float*)d_out;

    (void)in_sizes; (void)n_in; (void)out_size;

    impulse_fused_kernel<<<NBLK, TPB>>>(indices, embedding, ssm_decay, out);
}

// round 6
// speedup vs baseline: 1.0093x; 1.0093x over previous
#include <cuda_runtime.h>
#include <math.h>

// Problem constants (fixed by the dataset)
#define DIM      2048
#define SEQ      8192
#define NBLK     16               // blocks; each owns DIM/NBLK = 128 dims
#define TPB      256              // 8 token-groups x 32 dim-lanes
#define NLANE    32               // lanes per group; 32 * float4 = 128 dims
#define NGRP     8                // token groups per block
#define NTOK_FIX 64               // newest tokens processed unconditionally
// Tail truncation (only for tokens >= NTOK_FIX): keep weights > 2^-20.
// For the actual input ntok ~ 41 < 64, so the tail loop never runs and the
// effective truncation error is d^64 ~ 3e-10.
#define TCUT     20.0f

__device__ __forceinline__ float sigmoidf_(float x) {
    return 1.0f / (1.0f + expf(-x));
}

// out[dim] = tanh( (1-d) * sum_t d^t * emb[idx[SEQ-1-t]][dim] )
__global__ void __launch_bounds__(TPB)
impulse_fused_kernel(const int* __restrict__ idx,
                     const float* __restrict__ emb,
                     const float* __restrict__ ssm_decay,
                     float* __restrict__ out)
{
    __shared__ float4 red[NGRP - 1][NLANE];

    const int lane = threadIdx.x & (NLANE - 1);   // dim lane within block
    const int tg   = threadIdx.x >> 5;            // token group 0..7

    const int dim = blockIdx.x * (NLANE * 4) + lane * 4;

    // ---- Load stream: addresses depend ONLY on thread ids. These 8 idx
    // loads + 8 emb loads issue immediately and overlap the decay chain. ----
    const int NPT = NTOK_FIX / NGRP;              // 8 tokens per thread
    float4 x[NPT];
    #pragma unroll
    for (int j = 0; j < NPT; ++j) {
        const int t = tg + j * NGRP;
        const long long row =
            (long long)__ldg(idx + (SEQ - 1 - t)) * (long long)DIM;
        x[j] = *reinterpret_cast<const float4*>(emb + row + dim);
    }

    // ---- Decay chain: runs concurrently with the loads above. ----
    const float d   = sigmoidf_(ssm_decay[0]);
    const float l2d = log2f(d);                   // <= 0 since 0 < d <= 1

    const float wstep = exp2f((float)NGRP * l2d); // d^8
    float w = exp2f((float)tg * l2d);             // d^tg

    float ax = 0.0f, ay = 0.0f, az = 0.0f, aw = 0.0f;
    #pragma unroll
    for (int j = 0; j < NPT; ++j) {
        ax = fmaf(w, x[j].x, ax);
        ay = fmaf(w, x[j].y, ay);
        az = fmaf(w, x[j].z, az);
        aw = fmaf(w, x[j].w, aw);
        w *= wstep;
    }

    // ---- General-decay tail (empty for the actual input). ----
    const float nt = TCUT / (-l2d);               // inf if d == 1
    int ntok = (nt >= (float)SEQ) ? SEQ : ((int)nt + 1);
    for (int t = NTOK_FIX + tg; t < ntok; t += NGRP) {
        const long long row =
            (long long)__ldg(idx + (SEQ - 1 - t)) * (long long)DIM;
        const float4 v = *reinterpret_cast<const float4*>(emb + row + dim);
        const float wt = exp2f((float)t * l2d);
        ax = fmaf(wt, v.x, ax);
        ay = fmaf(wt, v.y, ay);
        az = fmaf(wt, v.z, az);
        aw = fmaf(wt, v.w, aw);
    }

    // ---- Cross-group reduction (fixed order -> deterministic). ----
    if (tg > 0) {
        float4 v; v.x = ax; v.y = ay; v.z = az; v.w = aw;
        red[tg - 1][lane] = v;
    }
    __syncthreads();

    if (tg == 0) {
        #pragma unroll
        for (int g = 0; g < NGRP - 1; ++g) {
            const float4 v = red[g][lane];
            ax += v.x; ay += v.y; az += v.z; aw += v.w;
        }
        const float s = 1.0f - d;
        float4 o;
        o.x = tanhf(s * ax);
        o.y = tanhf(s * ay);
        o.z = tanhf(s * az);
        o.w = tanhf(s * aw);
        *reinterpret_cast<float4*>(out + dim) = o;
    }
}

extern "C" void kernel_launch(void* const* d_in, const int* in_sizes, int n_in,
                              void* d_out, int out_size)
{
    const int*   indices   = (const int*)d_in[0];
    const float* embedding = (const float*)d_in[1];
    const float* ssm_decay = (const float*)d_in[2];
    float*       out       = (float*)d_out;

    (void)in_sizes; (void)n_in; (void)out_size;

    impulse_fused_kernel<<<NBLK, TPB>>>(indices, embedding, ssm_decay, out);
}

// round 7
// speedup vs baseline: 1.0435x; 1.0338x over previous
#include <cuda_runtime.h>
#include <math.h>

// Problem constants (fixed by the dataset)
#define DIM      2048
#define SEQ      8192
#define NBLK     16               // blocks; each owns DIM/NBLK = 128 dims
#define TPB      256              // 8 token-groups x 32 dim-lanes
#define NLANE    32               // lanes per group; 32 * float4 = 128 dims
#define NGRP     8                // token groups per block
#define NTOK_FIX 48               // newest tokens processed unconditionally
// NTOK_FIX truncation: d^48 ~ 7e-8 for the actual decay -> ~1e-7 relative
// contribution, ~1e4x under the 1e-3 tolerance. Tokens beyond NTOK_FIX are
// handled by the guarded tail loop whenever their weight exceeds 2^-TCUT
// (general-decay correctness; empty for the actual input).
#define TCUT     20.0f

__device__ __forceinline__ float sigmoidf_(float x) {
    return 1.0f / (1.0f + expf(-x));
}

// out[dim] = tanh( (1-d) * sum_t d^t * emb[idx[SEQ-1-t]][dim] )
__global__ void __launch_bounds__(TPB)
impulse_fused_kernel(const int* __restrict__ idx,
                     const float* __restrict__ emb,
                     const float* __restrict__ ssm_decay,
                     float* __restrict__ out)
{
    __shared__ float4 red[NGRP - 1][NLANE];

    // Issue the decay load FIRST so it flies alongside the gather stream.
    const float dec_raw = __ldg(ssm_decay);

    const int lane = threadIdx.x & (NLANE - 1);   // dim lane within block
    const int tg   = threadIdx.x >> 5;            // token group 0..7

    const int dim = blockIdx.x * (NLANE * 4) + lane * 4;

    // ---- Load stream: addresses depend ONLY on thread ids. All 6 idx
    // loads + 6 emb loads issue immediately, overlapping the decay math. ----
    const int NPT = NTOK_FIX / NGRP;              // 6 tokens per thread
    float4 x[NPT];
    #pragma unroll
    for (int j = 0; j < NPT; ++j) {
        const int t = tg + j * NGRP;
        const long long row =
            (long long)__ldg(idx + (SEQ - 1 - t)) * (long long)DIM;
        x[j] = *reinterpret_cast<const float4*>(emb + row + dim);
    }

    // ---- Decay chain: concurrent with the loads above. ----
    const float d   = sigmoidf_(dec_raw);
    const float l2d = log2f(d);                   // <= 0 since 0 < d <= 1

    const float wstep = exp2f((float)NGRP * l2d); // d^8
    float w = exp2f((float)tg * l2d);             // d^tg

    float ax = 0.0f, ay = 0.0f, az = 0.0f, aw = 0.0f;
    #pragma unroll
    for (int j = 0; j < NPT; ++j) {
        ax = fmaf(w, x[j].x, ax);
        ay = fmaf(w, x[j].y, ay);
        az = fmaf(w, x[j].z, az);
        aw = fmaf(w, x[j].w, aw);
        w *= wstep;
    }

    // ---- General-decay tail (empty for the actual input). ----
    const float nt = TCUT / (-l2d);               // inf if d == 1
    const int ntok = (nt >= (float)SEQ) ? SEQ : ((int)nt + 1);
    for (int t = NTOK_FIX + tg; t < ntok; t += NGRP) {
        const long long row =
            (long long)__ldg(idx + (SEQ - 1 - t)) * (long long)DIM;
        const float4 v = *reinterpret_cast<const float4*>(emb + row + dim);
        const float wt = exp2f((float)t * l2d);
        ax = fmaf(wt, v.x, ax);
        ay = fmaf(wt, v.y, ay);
        az = fmaf(wt, v.z, az);
        aw = fmaf(wt, v.w, aw);
    }

    // ---- Cross-group reduction (fixed order -> deterministic). ----
    if (tg > 0) {
        float4 v; v.x = ax; v.y = ay; v.z = az; v.w = aw;
        red[tg - 1][lane] = v;
    }
    __syncthreads();

    if (tg == 0) {
        #pragma unroll
        for (int g = 0; g < NGRP - 1; ++g) {
            const float4 v = red[g][lane];
            ax += v.x; ay += v.y; az += v.z; aw += v.w;
        }
        const float s = 1.0f - d;
        float4 o;
        o.x = tanhf(s * ax);
        o.y = tanhf(s * ay);
        o.z = tanhf(s * az);
        o.w = tanhf(s * aw);
        *reinterpret_cast<float4*>(out + dim) = o;
    }
}

extern "C" void kernel_launch(void* const* d_in, const int* in_sizes, int n_in,
                              void* d_out, int out_size)
{
    const int*   indices   = (const int*)d_in[0];
    const float* embedding = (const float*)d_in[1];
    const float* ssm_decay = (const float*)d_in[2];
    float*       out       = (float*)d_out;

    (void)in_sizes; (void)n_in; (void)out_size;

    impulse_fused_kernel<<<NBLK, TPB>>>(indices, embedding, ssm_decay, out);
}